// round 16
// baseline (speedup 1.0000x reference)
#include <cuda_runtime.h>
#include <cuda_bf16.h>
#include <math_constants.h>

// Problem constants
#define NN 100000
#define EE 1000000
#define ET (NN + EE)        // edges incl. self-loops = 1,100,000
#define GG 64
#define HH 64
#define DIN0 128
#define NBLK ((NN + 255) / 256)   // 391
#define FGRID ((NN + 127) / 128)  // 782

// ---------------- device scratch (no allocations allowed) ----------------
__device__ float g_h[(size_t)NN * HH];      // layer h (ping)
__device__ float g_h2[(size_t)NN * HH];     // layer h (pong)
__device__ float g_as[NN], g_ad[NN];        // alpha dots (ping)
__device__ float g_as2[NN], g_ad2[NN];      // alpha dots (pong)
__device__ float g_pool[GG * HH];
__device__ int   g_root[GG];

// CSR by dst (rebuilt every call; graph static across layers)
__device__ int g_deg[NN];
__device__ int g_tmp[NN];
__device__ int g_part[NBLK];
__device__ int g_row[NN + 1];
__device__ int g_cursor[NN];
__device__ int g_csr_src[ET];

// ---------------- helpers ----------------
__device__ __forceinline__ void atomicMaxF(float* addr, float v) {
    if (v >= 0.f) atomicMax((int*)addr, __float_as_int(v));
    else          atomicMin((unsigned int*)addr, __float_as_uint(v));
}

__device__ __forceinline__ unsigned long long pk2(float lo, float hi) {
    unsigned long long r;
    asm("mov.b64 %0, {%1,%2};" : "=l"(r) : "f"(lo), "f"(hi));
    return r;
}
__device__ __forceinline__ void unpk2(unsigned long long v, float& lo, float& hi) {
    asm("mov.b64 {%0,%1}, %2;" : "=f"(lo), "=f"(hi) : "l"(v));
}
__device__ __forceinline__ void fma2(unsigned long long& acc, unsigned long long a,
                                     unsigned long long b) {
    asm("fma.rn.f32x2 %0, %1, %2, %0;" : "+l"(acc) : "l"(a), "l"(b));
}

// ================= CSR build =================
__global__ void k_hist(const int* __restrict__ dst) {
    int e = blockIdx.x * blockDim.x + threadIdx.x;
    if (e >= ET) return;
    int d = (e < EE) ? dst[e] : (e - EE);
    atomicAdd(&g_deg[d], 1);
}

__global__ void k_scan_block() {
    __shared__ int sm[256];
    int t = threadIdx.x;
    int i = blockIdx.x * 256 + t;
    if (i < GG * HH) g_pool[i] = -CUDART_INF_F;
    if (i < GG) g_root[i] = 0x7FFFFFFF;
    int v = (i < NN) ? g_deg[i] : 0;
    sm[t] = v;
    __syncthreads();
#pragma unroll
    for (int off = 1; off < 256; off <<= 1) {
        int u = (t >= off) ? sm[t - off] : 0;
        __syncthreads();
        sm[t] += u;
        __syncthreads();
    }
    if (i < NN) g_tmp[i] = sm[t] - v;
    if (t == 255) g_part[blockIdx.x] = sm[255];
}

__global__ void k_scan_add() {
    __shared__ int s_sum;
    int t = threadIdx.x, bid = blockIdx.x;
    if (t == 0) s_sum = 0;
    __syncthreads();
    int v = 0;
    for (int j = t; j < bid; j += 256) v += g_part[j];
#pragma unroll
    for (int o = 16; o; o >>= 1) v += __shfl_xor_sync(0xFFFFFFFFu, v, o);
    if ((t & 31) == 0 && v) atomicAdd(&s_sum, v);
    __syncthreads();
    int i = bid * 256 + t;
    if (i < NN) {
        int r = g_tmp[i] + s_sum;
        g_row[i] = r;
        g_cursor[i] = r;
    }
    if (i == 0) g_row[NN] = ET;
}

__global__ void k_scatter(const int* __restrict__ src, const int* __restrict__ dst) {
    int e = blockIdx.x * blockDim.x + threadIdx.x;
    if (e >= ET) return;
    int s, d;
    if (e < EE) { s = src[e]; d = dst[e]; } else { s = d = e - EE; }
    int pos = atomicAdd(&g_cursor[d], 1);
    g_csr_src[pos] = s;
}

// ================= GEMM layer 1 (A = x from gmem) =================
// unchanged: 128x64 tile, 4x8 micro-tile, 3 CTAs/SM, double-buffered
template <int DIN>
__global__ void __launch_bounds__(256, 3) k_gemm(
        const float* __restrict__ A, const float* __restrict__ W,
        const float* __restrict__ asrc, const float* __restrict__ adst,
        float* __restrict__ hout, float* __restrict__ asout, float* __restrict__ adout) {
    __shared__ float As[2][16][256];
    __shared__ float Bs[2][16][64];

    int tid = threadIdx.x;
    int rg = tid >> 3;
    int cg = tid & 7;
    int row0 = blockIdx.x * 128;

    int lrow = tid >> 1;
    int lk   = (tid & 1) * 8;
    int slot = (lrow >> 2) * 8 + (lrow & 3);
    int bk = tid >> 4, bq = tid & 15;

    unsigned long long acc[4][4] = {};

    int arow = row0 + lrow;
    const float* aptr = (arow < NN) ? (A + (size_t)arow * DIN + lk) : nullptr;
    const float* bptr = W + (size_t)bk * 64 + bq * 4;

    constexpr int NIT = DIN / 16;
    float4 pa0, pa1, pb;

    pa0 = make_float4(0.f, 0.f, 0.f, 0.f);
    pa1 = pa0;
    if (aptr) { pa0 = *(const float4*)(aptr); pa1 = *(const float4*)(aptr + 4); }
    pb = *(const float4*)(bptr);
    {
        As[0][lk + 0][slot] = pa0.x;  As[0][lk + 1][slot] = pa0.y;
        As[0][lk + 2][slot] = pa0.z;  As[0][lk + 3][slot] = pa0.w;
        As[0][lk + 4][slot] = pa1.x;  As[0][lk + 5][slot] = pa1.y;
        As[0][lk + 6][slot] = pa1.z;  As[0][lk + 7][slot] = pa1.w;
        *(float4*)(&Bs[0][bk][bq * 4]) = pb;
    }
    __syncthreads();

    for (int it = 0; it < NIT; ++it) {
        int cur = it & 1;
        if (it + 1 < NIT) {
            int k0 = (it + 1) * 16;
            pa0 = make_float4(0.f, 0.f, 0.f, 0.f);
            pa1 = pa0;
            if (aptr) { pa0 = *(const float4*)(aptr + k0); pa1 = *(const float4*)(aptr + k0 + 4); }
            pb = *(const float4*)(bptr + (size_t)k0 * 64);
        }
#pragma unroll
        for (int k = 0; k < 16; k++) {
            float4 av  = *(float4*)(&As[cur][k][rg * 8]);
            float4 blo = *(float4*)(&Bs[cur][k][cg * 4]);
            float4 bhi = *(float4*)(&Bs[cur][k][32 + cg * 4]);
            unsigned long long b0 = pk2(blo.x, blo.y);
            unsigned long long b1 = pk2(blo.z, blo.w);
            unsigned long long b2 = pk2(bhi.x, bhi.y);
            unsigned long long b3 = pk2(bhi.z, bhi.w);
            float a[4] = {av.x, av.y, av.z, av.w};
#pragma unroll
            for (int r = 0; r < 4; r++) {
                unsigned long long ad = pk2(a[r], a[r]);
                fma2(acc[r][0], ad, b0);
                fma2(acc[r][1], ad, b1);
                fma2(acc[r][2], ad, b2);
                fma2(acc[r][3], ad, b3);
            }
        }
        if (it + 1 < NIT) {
            int nxt = cur ^ 1;
            As[nxt][lk + 0][slot] = pa0.x;  As[nxt][lk + 1][slot] = pa0.y;
            As[nxt][lk + 2][slot] = pa0.z;  As[nxt][lk + 3][slot] = pa0.w;
            As[nxt][lk + 4][slot] = pa1.x;  As[nxt][lk + 5][slot] = pa1.y;
            As[nxt][lk + 6][slot] = pa1.z;  As[nxt][lk + 7][slot] = pa1.w;
            *(float4*)(&Bs[nxt][bk][bq * 4]) = pb;
        }
        __syncthreads();
    }

    float4 aslo = *(const float4*)(asrc + cg * 4);
    float4 ashi = *(const float4*)(asrc + 32 + cg * 4);
    float4 adlo = *(const float4*)(adst + cg * 4);
    float4 adhi = *(const float4*)(adst + 32 + cg * 4);
    int lane = tid & 31;
    unsigned seg_mask = 0xFFu << (lane & 24);

#pragma unroll
    for (int i = 0; i < 4; i++) {
        int r = row0 + rg * 4 + i;
        float4 vlo, vhi;
        unpk2(acc[i][0], vlo.x, vlo.y);
        unpk2(acc[i][1], vlo.z, vlo.w);
        unpk2(acc[i][2], vhi.x, vhi.y);
        unpk2(acc[i][3], vhi.z, vhi.w);
        if (r < NN) {
            float* hp = hout + (size_t)r * 64;
            *(float4*)(hp + cg * 4)      = vlo;
            *(float4*)(hp + 32 + cg * 4) = vhi;
        }
        float s = vlo.x * aslo.x + vlo.y * aslo.y + vlo.z * aslo.z + vlo.w * aslo.w
                + vhi.x * ashi.x + vhi.y * ashi.y + vhi.z * ashi.z + vhi.w * ashi.w;
        float d = vlo.x * adlo.x + vlo.y * adlo.y + vlo.z * adlo.z + vlo.w * adlo.w
                + vhi.x * adhi.x + vhi.y * adhi.y + vhi.z * adhi.z + vhi.w * adhi.w;
#pragma unroll
        for (int o = 4; o; o >>= 1) {
            s += __shfl_xor_sync(seg_mask, s, o, 8);
            d += __shfl_xor_sync(seg_mask, d, o, 8);
        }
        if (cg == 0 && r < NN) { asout[r] = s; adout[r] = d; }
    }
}

// ================= shared agg body: softmax-weighted sum for one node =================
__device__ __forceinline__ float4 agg_node(
        int node, int ln, unsigned seg_mask,
        const float* __restrict__ h_in, const float* __restrict__ as_in,
        const float* __restrict__ ad_in, const float* __restrict__ bprev) {
    int row = g_row[node], end = g_row[node + 1];
    int deg = end - row;
    float ad = ad_in[node];

    float m = -CUDART_INF_F;
    float myv = 0.f; int mys = 0;
    for (int i = row + ln; i < end; i += 16) {
        int s = __ldg(&g_csr_src[i]);
        float v = __ldg(&as_in[s]) + ad;
        v = fmaxf(v, 0.2f * v);          // leaky_relu(0.2)
        mys = s; myv = v;
        m = fmaxf(m, v);
    }
#pragma unroll
    for (int o = 8; o; o >>= 1) m = fmaxf(m, __shfl_xor_sync(seg_mask, m, o, 16));

    float den = 0.f;
    unsigned long long acc01 = 0, acc23 = 0;

    if (deg <= 16) {
        float num = 0.f; int s = 0;
        if (ln < deg) { num = __expf(myv - m); s = mys; }
        den = num;
        int j = 0;
        for (; j + 4 <= deg; j += 4) {
            float c0 = __shfl_sync(seg_mask, num, j + 0, 16);
            float c1 = __shfl_sync(seg_mask, num, j + 1, 16);
            float c2 = __shfl_sync(seg_mask, num, j + 2, 16);
            float c3 = __shfl_sync(seg_mask, num, j + 3, 16);
            int  s0 = __shfl_sync(seg_mask, s, j + 0, 16);
            int  s1 = __shfl_sync(seg_mask, s, j + 1, 16);
            int  s2 = __shfl_sync(seg_mask, s, j + 2, 16);
            int  s3 = __shfl_sync(seg_mask, s, j + 3, 16);
            float4 h0 = __ldg((const float4*)(h_in + (size_t)s0 * 64) + ln);
            float4 h1 = __ldg((const float4*)(h_in + (size_t)s1 * 64) + ln);
            float4 h2 = __ldg((const float4*)(h_in + (size_t)s2 * 64) + ln);
            float4 h3 = __ldg((const float4*)(h_in + (size_t)s3 * 64) + ln);
            fma2(acc01, pk2(h0.x, h0.y), pk2(c0, c0));
            fma2(acc23, pk2(h0.z, h0.w), pk2(c0, c0));
            fma2(acc01, pk2(h1.x, h1.y), pk2(c1, c1));
            fma2(acc23, pk2(h1.z, h1.w), pk2(c1, c1));
            fma2(acc01, pk2(h2.x, h2.y), pk2(c2, c2));
            fma2(acc23, pk2(h2.z, h2.w), pk2(c2, c2));
            fma2(acc01, pk2(h3.x, h3.y), pk2(c3, c3));
            fma2(acc23, pk2(h3.z, h3.w), pk2(c3, c3));
        }
        for (; j < deg; j++) {
            float c = __shfl_sync(seg_mask, num, j, 16);
            int  ss = __shfl_sync(seg_mask, s, j, 16);
            float4 hv = __ldg((const float4*)(h_in + (size_t)ss * 64) + ln);
            unsigned long long cc = pk2(c, c);
            fma2(acc01, pk2(hv.x, hv.y), cc);
            fma2(acc23, pk2(hv.z, hv.w), cc);
        }
    } else {
        for (int base = row; base < end; base += 16) {
            int i = base + ln;
            int s = 0; float num = 0.f;
            if (i < end) {
                s = __ldg(&g_csr_src[i]);
                float v = __ldg(&as_in[s]) + ad;
                v = fmaxf(v, 0.2f * v);
                num = __expf(v - m);
            }
            den += num;
            int cnt = min(16, end - base);
            int j = 0;
            for (; j + 4 <= cnt; j += 4) {
                float c0 = __shfl_sync(seg_mask, num, j + 0, 16);
                float c1 = __shfl_sync(seg_mask, num, j + 1, 16);
                float c2 = __shfl_sync(seg_mask, num, j + 2, 16);
                float c3 = __shfl_sync(seg_mask, num, j + 3, 16);
                int  s0 = __shfl_sync(seg_mask, s, j + 0, 16);
                int  s1 = __shfl_sync(seg_mask, s, j + 1, 16);
                int  s2 = __shfl_sync(seg_mask, s, j + 2, 16);
                int  s3 = __shfl_sync(seg_mask, s, j + 3, 16);
                float4 h0 = __ldg((const float4*)(h_in + (size_t)s0 * 64) + ln);
                float4 h1 = __ldg((const float4*)(h_in + (size_t)s1 * 64) + ln);
                float4 h2 = __ldg((const float4*)(h_in + (size_t)s2 * 64) + ln);
                float4 h3 = __ldg((const float4*)(h_in + (size_t)s3 * 64) + ln);
                fma2(acc01, pk2(h0.x, h0.y), pk2(c0, c0));
                fma2(acc23, pk2(h0.z, h0.w), pk2(c0, c0));
                fma2(acc01, pk2(h1.x, h1.y), pk2(c1, c1));
                fma2(acc23, pk2(h1.z, h1.w), pk2(c1, c1));
                fma2(acc01, pk2(h2.x, h2.y), pk2(c2, c2));
                fma2(acc23, pk2(h2.z, h2.w), pk2(c2, c2));
                fma2(acc01, pk2(h3.x, h3.y), pk2(c3, c3));
                fma2(acc23, pk2(h3.z, h3.w), pk2(c3, c3));
            }
            for (; j < cnt; j++) {
                float c = __shfl_sync(seg_mask, num, j, 16);
                int  ss = __shfl_sync(seg_mask, s, j, 16);
                float4 hv = __ldg((const float4*)(h_in + (size_t)ss * 64) + ln);
                unsigned long long cc = pk2(c, c);
                fma2(acc01, pk2(hv.x, hv.y), cc);
                fma2(acc23, pk2(hv.z, hv.w), cc);
            }
        }
    }
#pragma unroll
    for (int o = 8; o; o >>= 1) den += __shfl_xor_sync(seg_mask, den, o, 16);

    float inv = 1.f / (den + 1e-16f);
    float4 a, b4 = ((const float4*)bprev)[ln];
    unpk2(acc01, a.x, a.y);
    unpk2(acc23, a.z, a.w);
    float4 o4;
    o4.x = fmaxf(a.x * inv + b4.x, 0.f);
    o4.y = fmaxf(a.y * inv + b4.y, 0.f);
    o4.z = fmaxf(a.z * inv + b4.z, 0.f);
    o4.w = fmaxf(a.w * inv + b4.w, 0.f);
    return o4;
}

// ================= fused agg(layer l) + gemm(layer l+1) =================
// CTA covers 128 nodes: agg into smem (permuted slots), sync, GEMM with A
// resident. DIN = 64. Dynamic smem: act_s[128][68] + Bs[64][68].
#define F_SMEM ((128 * 68 + 64 * 68) * 4)

__global__ void __launch_bounds__(256, 3) k_fused_mid(
        const float* __restrict__ bprev,
        const float* __restrict__ W,
        const float* __restrict__ asrc, const float* __restrict__ adst,
        const float* __restrict__ h_in, const float* __restrict__ as_in,
        const float* __restrict__ ad_in,
        float* __restrict__ h_out, float* __restrict__ as_out,
        float* __restrict__ ad_out) {
    extern __shared__ float smf[];
    float* act_s = smf;                 // [128 phys][68]
    float* Bs    = smf + 128 * 68;      // [64][68]

    int tid = threadIdx.x;
    int row0 = blockIdx.x * 128;

    // stage W (64x64) once
    {
        int wr = tid >> 2;
        int wc = (tid & 3) * 4;
#pragma unroll
        for (int q = 0; q < 4; q++) {
            float4 wv = *(const float4*)(W + (size_t)wr * 64 + wc + q * 16);
            *(float4*)(Bs + wr * 68 + wc + q * 16) = wv;
        }
    }

    // ---- agg phase: 8 passes x 16 nodes ----
    int ln = tid & 15;
    unsigned seg_mask = 0xFFFFu << (tid & 16);
#pragma unroll 1
    for (int p = 0; p < 8; p++) {
        int nl = p * 16 + (tid >> 4);
        int node = row0 + nl;
        float4 o4 = make_float4(0.f, 0.f, 0.f, 0.f);
        if (node < NN)
            o4 = agg_node(node, ln, seg_mask, h_in, as_in, ad_in, bprev);
        int phys = (nl & 3) * 32 + (nl >> 2);
        *(float4*)(act_s + phys * 68 + ln * 4) = o4;
    }
    __syncthreads();

    // ---- gemm phase: C = act @ W (no barriers in loop) ----
    int rg = tid >> 3;
    int cg = tid & 7;
    unsigned long long acc[4][4] = {};
#pragma unroll 4
    for (int kq = 0; kq < 16; kq++) {
        float4 a[4];
#pragma unroll
        for (int r = 0; r < 4; r++) {
            int phys = r * 32 + rg;          // row rg*4+r -> phys
            a[r] = *(float4*)(act_s + phys * 68 + kq * 4);
        }
#pragma unroll
        for (int j = 0; j < 4; j++) {
            int k = kq * 4 + j;
            float4 blo = *(float4*)(Bs + k * 68 + cg * 4);
            float4 bhi = *(float4*)(Bs + k * 68 + 32 + cg * 4);
            unsigned long long b0 = pk2(blo.x, blo.y);
            unsigned long long b1 = pk2(blo.z, blo.w);
            unsigned long long b2 = pk2(bhi.x, bhi.y);
            unsigned long long b3 = pk2(bhi.z, bhi.w);
#pragma unroll
            for (int r = 0; r < 4; r++) {
                float aj = ((const float*)&a[r])[j];
                unsigned long long ad2 = pk2(aj, aj);
                fma2(acc[r][0], ad2, b0);
                fma2(acc[r][1], ad2, b1);
                fma2(acc[r][2], ad2, b2);
                fma2(acc[r][3], ad2, b3);
            }
        }
    }

    // epilogue: store h, alpha dots
    float4 aslo = *(const float4*)(asrc + cg * 4);
    float4 ashi = *(const float4*)(asrc + 32 + cg * 4);
    float4 adlo = *(const float4*)(adst + cg * 4);
    float4 adhi = *(const float4*)(adst + 32 + cg * 4);
    int lane = tid & 31;
    unsigned emask = 0xFFu << (lane & 24);

#pragma unroll
    for (int i = 0; i < 4; i++) {
        int r = row0 + rg * 4 + i;
        float4 vlo, vhi;
        unpk2(acc[i][0], vlo.x, vlo.y);
        unpk2(acc[i][1], vlo.z, vlo.w);
        unpk2(acc[i][2], vhi.x, vhi.y);
        unpk2(acc[i][3], vhi.z, vhi.w);
        if (r < NN) {
            float* hp = h_out + (size_t)r * 64;
            *(float4*)(hp + cg * 4)      = vlo;
            *(float4*)(hp + 32 + cg * 4) = vhi;
        }
        float s = vlo.x * aslo.x + vlo.y * aslo.y + vlo.z * aslo.z + vlo.w * aslo.w
                + vhi.x * ashi.x + vhi.y * ashi.y + vhi.z * ashi.z + vhi.w * ashi.w;
        float d = vlo.x * adlo.x + vlo.y * adlo.y + vlo.z * adlo.z + vlo.w * adlo.w
                + vhi.x * adhi.x + vhi.y * adhi.y + vhi.z * adhi.z + vhi.w * adhi.w;
#pragma unroll
        for (int o = 4; o; o >>= 1) {
            s += __shfl_xor_sync(emask, s, o, 8);
            d += __shfl_xor_sync(emask, d, o, 8);
        }
        if (cg == 0 && r < NN) { as_out[r] = s; ad_out[r] = d; }
    }
}

// ================= fused agg(layer 3) + global max pool + root =================
__global__ void k_fused_last(
        const float* __restrict__ bprev,
        const float* __restrict__ h_in, const float* __restrict__ as_in,
        const float* __restrict__ ad_in,
        const int* __restrict__ batch) {
    int tid = threadIdx.x;
    int row0 = blockIdx.x * 128;
    int ln = tid & 15;
    unsigned seg_mask = 0xFFFFu << (tid & 16);

    int curg = -1;
    float4 cur = make_float4(0.f, 0.f, 0.f, 0.f);

#pragma unroll 1
    for (int p = 0; p < 8; p++) {
        int node = row0 + p * 16 + (tid >> 4);
        if (node >= NN) continue;       // uniform within 16-lane segment
        float4 o4 = agg_node(node, ln, seg_mask, h_in, as_in, ad_in, bprev);
        int g = batch[node];
        if (ln == 0 && (node == 0 || batch[node - 1] != g))
            atomicMin(&g_root[g], node);
        if (g != curg) {
            if (curg >= 0) {
                float* pp = g_pool + curg * 64 + ln * 4;
                atomicMaxF(pp + 0, cur.x); atomicMaxF(pp + 1, cur.y);
                atomicMaxF(pp + 2, cur.z); atomicMaxF(pp + 3, cur.w);
            }
            curg = g; cur = o4;
        } else {
            cur.x = fmaxf(cur.x, o4.x); cur.y = fmaxf(cur.y, o4.y);
            cur.z = fmaxf(cur.z, o4.z); cur.w = fmaxf(cur.w, o4.w);
        }
    }
    if (curg >= 0) {
        float* pp = g_pool + curg * 64 + ln * 4;
        atomicMaxF(pp + 0, cur.x); atomicMaxF(pp + 1, cur.y);
        atomicMaxF(pp + 2, cur.z); atomicMaxF(pp + 3, cur.w);
    }
}

// ================= head =================
__global__ void k_head(const float* __restrict__ x,
                       const float* __restrict__ lnW, const float* __restrict__ lnb,
                       const float* __restrict__ l0W, const float* __restrict__ l0b,
                       const float* __restrict__ l1W, const float* __restrict__ l1b,
                       float* __restrict__ out) {
    int g = blockIdx.x;
    int c = threadIdx.x;
    __shared__ float red[2];

    float acc = l0b[c];
#pragma unroll 8
    for (int k = 0; k < 64; k++) acc += g_pool[g * 64 + k] * l0W[k * 64 + c];
    float hp = fmaxf(acc, 0.f);

    const float* xr = x + (size_t)g_root[g] * DIN0;
    float accn = lnb[c];
#pragma unroll 8
    for (int k = 0; k < 128; k++) accn += xr[k] * lnW[k * 64 + c];
    float nw = fmaxf(accn, 0.f);

    float p = hp * l1W[c] + nw * l1W[64 + c];
#pragma unroll
    for (int o = 16; o; o >>= 1) p += __shfl_xor_sync(0xFFFFFFFFu, p, o);
    if ((c & 31) == 0) red[c >> 5] = p;
    __syncthreads();
    if (c == 0) {
        float z = red[0] + red[1] + l1b[0];
        out[g] = 1.f / (1.f + __expf(-z));
    }
}

// ================= launch =================
extern "C" void kernel_launch(void* const* d_in, const int* in_sizes, int n_in,
                              void* d_out, int out_size) {
    const float* x      = (const float*)d_in[0];
    const int*   adj    = (const int*)d_in[1];
    const int*   batch  = (const int*)d_in[2];
    const float* W1     = (const float*)d_in[3];
    const float* asrc1  = (const float*)d_in[4];
    const float* adst1  = (const float*)d_in[5];
    const float* b1     = (const float*)d_in[6];
    const float* W2     = (const float*)d_in[7];
    const float* asrc2  = (const float*)d_in[8];
    const float* adst2  = (const float*)d_in[9];
    const float* b2     = (const float*)d_in[10];
    const float* W3     = (const float*)d_in[11];
    const float* asrc3  = (const float*)d_in[12];
    const float* adst3  = (const float*)d_in[13];
    const float* b3     = (const float*)d_in[14];
    const float* lnW    = (const float*)d_in[15];
    const float* lnb    = (const float*)d_in[16];
    const float* l0W    = (const float*)d_in[17];
    const float* l0b    = (const float*)d_in[18];
    const float* l1W    = (const float*)d_in[19];
    const float* l1b    = (const float*)d_in[20];
    float* out = (float*)d_out;

    const int* src = adj;
    const int* dst = adj + EE;

    void *p_deg, *p_h, *p_h2, *p_as, *p_ad, *p_as2, *p_ad2;
    cudaGetSymbolAddress(&p_deg, g_deg);
    cudaGetSymbolAddress(&p_h,   g_h);
    cudaGetSymbolAddress(&p_h2,  g_h2);
    cudaGetSymbolAddress(&p_as,  g_as);
    cudaGetSymbolAddress(&p_ad,  g_ad);
    cudaGetSymbolAddress(&p_as2, g_as2);
    cudaGetSymbolAddress(&p_ad2, g_ad2);

    cudaFuncSetAttribute(k_fused_mid, cudaFuncAttributeMaxDynamicSharedMemorySize, F_SMEM);

    const int EDGE_GRID = (ET + 255) / 256;           // 4297

    // ---- fork: CSR build (s2) overlaps gemm1 (main) ----
    cudaStream_t s2;
    cudaStreamCreateWithFlags(&s2, cudaStreamNonBlocking);
    cudaEvent_t evF, evJ;
    cudaEventCreateWithFlags(&evF, cudaEventDisableTiming);
    cudaEventCreateWithFlags(&evJ, cudaEventDisableTiming);

    cudaEventRecord(evF, 0);
    cudaStreamWaitEvent(s2, evF, 0);

    cudaMemsetAsync(p_deg, 0, NN * sizeof(int), s2);
    k_hist<<<EDGE_GRID, 256, 0, s2>>>(dst);
    k_scan_block<<<NBLK, 256, 0, s2>>>();             // also inits pool/root
    k_scan_add<<<NBLK, 256, 0, s2>>>();

    // main: gemm1 (profiled slot; unchanged kernel as control)
    k_gemm<128><<<FGRID, 256>>>(x, W1, asrc1, adst1,
                                (float*)p_h, (float*)p_as, (float*)p_ad);

    k_scatter<<<EDGE_GRID, 256, 0, s2>>>(src, dst);
    cudaEventRecord(evJ, s2);
    cudaStreamWaitEvent(0, evJ, 0);                   // join before F1

    // ---- fused layer boundaries ----
    k_fused_mid<<<FGRID, 256, F_SMEM>>>(b1, W2, asrc2, adst2,
        (const float*)p_h, (const float*)p_as, (const float*)p_ad,
        (float*)p_h2, (float*)p_as2, (float*)p_ad2);

    k_fused_mid<<<FGRID, 256, F_SMEM>>>(b2, W3, asrc3, adst3,
        (const float*)p_h2, (const float*)p_as2, (const float*)p_ad2,
        (float*)p_h, (float*)p_as, (float*)p_ad);

    k_fused_last<<<FGRID, 256>>>(b3,
        (const float*)p_h, (const float*)p_as, (const float*)p_ad, batch);

    // ---- head ----
    k_head<<<GG, 64>>>(x, lnW, lnb, l0W, l0b, l1W, l1b, out);

    cudaEventDestroy(evF);
    cudaEventDestroy(evJ);
    cudaStreamDestroy(s2);
}

// round 17
// speedup vs baseline: 1.0545x; 1.0545x over previous
#include <cuda_runtime.h>
#include <cuda_bf16.h>
#include <math_constants.h>

// Problem constants
#define NN 100000
#define EE 1000000
#define ET (NN + EE)        // edges incl. self-loops = 1,100,000
#define GG 64
#define HH 64
#define DIN0 128
#define NBLK ((NN + 255) / 256)   // 391

// ---------------- device scratch (no allocations allowed) ----------------
__device__ float g_h[(size_t)NN * HH];      // h = x @ W (pre-bias)
__device__ float g_act[(size_t)NN * HH];    // relu(agg + b) -> next layer input
__device__ float g_as[NN];                  // h . a_src per node
__device__ float g_ad[NN];                  // h . a_dst per node
__device__ float g_pool[GG * HH];
__device__ float g_news[GG * HH];           // relu(x[root] @ lnW + lnb)
__device__ int   g_root[GG];

// CSR by dst (rebuilt every call; graph static across layers)
__device__ int g_deg[NN];
__device__ int g_tmp[NN];          // block-local exclusive scan
__device__ int g_part[NBLK];       // per-block sums
__device__ int g_row[NN + 1];
__device__ int g_cursor[NN];
__device__ int g_csr_src[ET];

// ---------------- helpers ----------------
__device__ __forceinline__ void atomicMaxF(float* addr, float v) {
    if (v >= 0.f) atomicMax((int*)addr, __float_as_int(v));
    else          atomicMin((unsigned int*)addr, __float_as_uint(v));
}

__device__ __forceinline__ unsigned long long pk2(float lo, float hi) {
    unsigned long long r;
    asm("mov.b64 %0, {%1,%2};" : "=l"(r) : "f"(lo), "f"(hi));
    return r;
}
__device__ __forceinline__ void unpk2(unsigned long long v, float& lo, float& hi) {
    asm("mov.b64 {%0,%1}, %2;" : "=f"(lo), "=f"(hi) : "l"(v));
}
__device__ __forceinline__ void fma2(unsigned long long& acc, unsigned long long a,
                                     unsigned long long b) {
    asm("fma.rn.f32x2 %0, %1, %2, %0;" : "+l"(acc) : "l"(a), "l"(b));
}

// ================= CSR build =================
__global__ void k_hist(const int* __restrict__ dst) {
    int e = blockIdx.x * blockDim.x + threadIdx.x;
    if (e >= ET) return;
    int d = (e < EE) ? dst[e] : (e - EE);
    atomicAdd(&g_deg[d], 1);
}

__global__ void k_scan_block() {
    __shared__ int sm[256];
    int t = threadIdx.x;
    int i = blockIdx.x * 256 + t;
    if (i < GG * HH) g_pool[i] = -CUDART_INF_F;
    if (i < GG) g_root[i] = 0x7FFFFFFF;
    int v = (i < NN) ? g_deg[i] : 0;
    sm[t] = v;
    __syncthreads();
#pragma unroll
    for (int off = 1; off < 256; off <<= 1) {
        int u = (t >= off) ? sm[t - off] : 0;
        __syncthreads();
        sm[t] += u;
        __syncthreads();
    }
    if (i < NN) g_tmp[i] = sm[t] - v;
    if (t == 255) g_part[blockIdx.x] = sm[255];
}

__global__ void k_scan_add() {
    __shared__ int s_sum;
    int t = threadIdx.x, bid = blockIdx.x;
    if (t == 0) s_sum = 0;
    __syncthreads();
    int v = 0;
    for (int j = t; j < bid; j += 256) v += g_part[j];
#pragma unroll
    for (int o = 16; o; o >>= 1) v += __shfl_xor_sync(0xFFFFFFFFu, v, o);
    if ((t & 31) == 0 && v) atomicAdd(&s_sum, v);
    __syncthreads();
    int i = bid * 256 + t;
    if (i < NN) {
        int r = g_tmp[i] + s_sum;
        g_row[i] = r;
        g_cursor[i] = r;
    }
    if (i == 0) g_row[NN] = ET;
}

__global__ void k_scatter(const int* __restrict__ src, const int* __restrict__ dst) {
    int e = blockIdx.x * blockDim.x + threadIdx.x;
    if (e >= ET) return;
    int s, d;
    if (e < EE) { s = src[e]; d = dst[e]; } else { s = d = e - EE; }
    int pos = atomicAdd(&g_cursor[d], 1);
    g_csr_src[pos] = s;
}

// ================= root detection (batch only; runs on side stream) =================
__global__ void k_root(const int* __restrict__ batch) {
    int i = blockIdx.x * blockDim.x + threadIdx.x;
    if (i >= NN) return;
    int g = batch[i];
    if (i == 0 || batch[i - 1] != g) atomicMin(&g_root[g], i);
}

// ================= news head branch (x, root only; runs on side stream) =================
__global__ void k_news(const float* __restrict__ x,
                       const float* __restrict__ lnW, const float* __restrict__ lnb) {
    int g = blockIdx.x;
    int c = threadIdx.x;   // 0..63
    const float* xr = x + (size_t)g_root[g] * DIN0;
    float acc = lnb[c];
#pragma unroll 8
    for (int k = 0; k < 128; k++) acc += xr[k] * lnW[k * 64 + c];
    g_news[g * 64 + c] = fmaxf(acc, 0.f);
}

// ================= GEMM + fused alpha epilogue =================
// (unchanged — 128x64 tile, 4x8 micro-tile, 3 CTAs/SM, double-buffered)
template <int DIN>
__global__ void __launch_bounds__(256, 3) k_gemm(
        const float* __restrict__ A, const float* __restrict__ W,
        const float* __restrict__ asrc, const float* __restrict__ adst) {
    __shared__ float As[2][16][256];
    __shared__ float Bs[2][16][64];

    const float* Ap = A ? A : g_act;
    int tid = threadIdx.x;
    int rg = tid >> 3;
    int cg = tid & 7;
    int row0 = blockIdx.x * 128;

    int lrow = tid >> 1;
    int lk   = (tid & 1) * 8;
    int slot = (lrow >> 2) * 8 + (lrow & 3);
    int bk = tid >> 4, bq = tid & 15;

    unsigned long long acc[4][4] = {};

    int arow = row0 + lrow;
    const float* aptr = (arow < NN) ? (Ap + (size_t)arow * DIN + lk) : nullptr;
    const float* bptr = W + (size_t)bk * 64 + bq * 4;

    constexpr int NIT = DIN / 16;
    float4 pa0, pa1, pb;

    pa0 = make_float4(0.f, 0.f, 0.f, 0.f);
    pa1 = pa0;
    if (aptr) { pa0 = *(const float4*)(aptr); pa1 = *(const float4*)(aptr + 4); }
    pb = *(const float4*)(bptr);
    {
        As[0][lk + 0][slot] = pa0.x;  As[0][lk + 1][slot] = pa0.y;
        As[0][lk + 2][slot] = pa0.z;  As[0][lk + 3][slot] = pa0.w;
        As[0][lk + 4][slot] = pa1.x;  As[0][lk + 5][slot] = pa1.y;
        As[0][lk + 6][slot] = pa1.z;  As[0][lk + 7][slot] = pa1.w;
        *(float4*)(&Bs[0][bk][bq * 4]) = pb;
    }
    __syncthreads();

    for (int it = 0; it < NIT; ++it) {
        int cur = it & 1;
        if (it + 1 < NIT) {
            int k0 = (it + 1) * 16;
            pa0 = make_float4(0.f, 0.f, 0.f, 0.f);
            pa1 = pa0;
            if (aptr) { pa0 = *(const float4*)(aptr + k0); pa1 = *(const float4*)(aptr + k0 + 4); }
            pb = *(const float4*)(bptr + (size_t)k0 * 64);
        }
#pragma unroll
        for (int k = 0; k < 16; k++) {
            float4 av  = *(float4*)(&As[cur][k][rg * 8]);
            float4 blo = *(float4*)(&Bs[cur][k][cg * 4]);
            float4 bhi = *(float4*)(&Bs[cur][k][32 + cg * 4]);
            unsigned long long b0 = pk2(blo.x, blo.y);
            unsigned long long b1 = pk2(blo.z, blo.w);
            unsigned long long b2 = pk2(bhi.x, bhi.y);
            unsigned long long b3 = pk2(bhi.z, bhi.w);
            float a[4] = {av.x, av.y, av.z, av.w};
#pragma unroll
            for (int r = 0; r < 4; r++) {
                unsigned long long ad = pk2(a[r], a[r]);
                fma2(acc[r][0], ad, b0);
                fma2(acc[r][1], ad, b1);
                fma2(acc[r][2], ad, b2);
                fma2(acc[r][3], ad, b3);
            }
        }
        if (it + 1 < NIT) {
            int nxt = cur ^ 1;
            As[nxt][lk + 0][slot] = pa0.x;  As[nxt][lk + 1][slot] = pa0.y;
            As[nxt][lk + 2][slot] = pa0.z;  As[nxt][lk + 3][slot] = pa0.w;
            As[nxt][lk + 4][slot] = pa1.x;  As[nxt][lk + 5][slot] = pa1.y;
            As[nxt][lk + 6][slot] = pa1.z;  As[nxt][lk + 7][slot] = pa1.w;
            *(float4*)(&Bs[nxt][bk][bq * 4]) = pb;
        }
        __syncthreads();
    }

    float4 aslo = *(const float4*)(asrc + cg * 4);
    float4 ashi = *(const float4*)(asrc + 32 + cg * 4);
    float4 adlo = *(const float4*)(adst + cg * 4);
    float4 adhi = *(const float4*)(adst + 32 + cg * 4);
    int lane = tid & 31;
    unsigned seg_mask = 0xFFu << (lane & 24);

#pragma unroll
    for (int i = 0; i < 4; i++) {
        int r = row0 + rg * 4 + i;
        float4 vlo, vhi;
        unpk2(acc[i][0], vlo.x, vlo.y);
        unpk2(acc[i][1], vlo.z, vlo.w);
        unpk2(acc[i][2], vhi.x, vhi.y);
        unpk2(acc[i][3], vhi.z, vhi.w);
        if (r < NN) {
            float* hp = g_h + (size_t)r * 64;
            *(float4*)(hp + cg * 4)      = vlo;
            *(float4*)(hp + 32 + cg * 4) = vhi;
        }
        float s = vlo.x * aslo.x + vlo.y * aslo.y + vlo.z * aslo.z + vlo.w * aslo.w
                + vhi.x * ashi.x + vhi.y * ashi.y + vhi.z * ashi.z + vhi.w * ashi.w;
        float d = vlo.x * adlo.x + vlo.y * adlo.y + vlo.z * adlo.z + vlo.w * adlo.w
                + vhi.x * adhi.x + vhi.y * adhi.y + vhi.z * adhi.z + vhi.w * adhi.w;
#pragma unroll
        for (int o = 4; o; o >>= 1) {
            s += __shfl_xor_sync(seg_mask, s, o, 8);
            d += __shfl_xor_sync(seg_mask, d, o, 8);
        }
        if (cg == 0 && r < NN) { g_as[r] = s; g_ad[r] = d; }
    }
}

// ================= fused GAT aggregation: 16 lanes per dst node =================
// (unchanged from R15: x4-unrolled gathers, __ldg path)
__global__ void k_gat_agg(const float* __restrict__ b) {
    int t = blockIdx.x * blockDim.x + threadIdx.x;
    int node = t >> 4;
    int ln = threadIdx.x & 15;
    if (node >= NN) return;
    unsigned seg_mask = 0xFFFFu << (threadIdx.x & 16);

    int row = g_row[node], end = g_row[node + 1];
    int deg = end - row;
    float ad = g_ad[node];

    float m = -CUDART_INF_F;
    float myv = 0.f; int mys = 0;
    for (int i = row + ln; i < end; i += 16) {
        int s = __ldg(&g_csr_src[i]);
        float v = __ldg(&g_as[s]) + ad;
        v = fmaxf(v, 0.2f * v);          // leaky_relu(0.2)
        mys = s; myv = v;
        m = fmaxf(m, v);
    }
#pragma unroll
    for (int o = 8; o; o >>= 1) m = fmaxf(m, __shfl_xor_sync(seg_mask, m, o, 16));

    float den = 0.f;
    unsigned long long acc01 = 0, acc23 = 0;

    if (deg <= 16) {
        float num = 0.f; int s = 0;
        if (ln < deg) { num = __expf(myv - m); s = mys; }
        den = num;
        int j = 0;
        for (; j + 4 <= deg; j += 4) {
            float c0 = __shfl_sync(seg_mask, num, j + 0, 16);
            float c1 = __shfl_sync(seg_mask, num, j + 1, 16);
            float c2 = __shfl_sync(seg_mask, num, j + 2, 16);
            float c3 = __shfl_sync(seg_mask, num, j + 3, 16);
            int  s0 = __shfl_sync(seg_mask, s, j + 0, 16);
            int  s1 = __shfl_sync(seg_mask, s, j + 1, 16);
            int  s2 = __shfl_sync(seg_mask, s, j + 2, 16);
            int  s3 = __shfl_sync(seg_mask, s, j + 3, 16);
            float4 h0 = __ldg((const float4*)(g_h + (size_t)s0 * 64) + ln);
            float4 h1 = __ldg((const float4*)(g_h + (size_t)s1 * 64) + ln);
            float4 h2 = __ldg((const float4*)(g_h + (size_t)s2 * 64) + ln);
            float4 h3 = __ldg((const float4*)(g_h + (size_t)s3 * 64) + ln);
            fma2(acc01, pk2(h0.x, h0.y), pk2(c0, c0));
            fma2(acc23, pk2(h0.z, h0.w), pk2(c0, c0));
            fma2(acc01, pk2(h1.x, h1.y), pk2(c1, c1));
            fma2(acc23, pk2(h1.z, h1.w), pk2(c1, c1));
            fma2(acc01, pk2(h2.x, h2.y), pk2(c2, c2));
            fma2(acc23, pk2(h2.z, h2.w), pk2(c2, c2));
            fma2(acc01, pk2(h3.x, h3.y), pk2(c3, c3));
            fma2(acc23, pk2(h3.z, h3.w), pk2(c3, c3));
        }
        for (; j < deg; j++) {
            float c = __shfl_sync(seg_mask, num, j, 16);
            int  ss = __shfl_sync(seg_mask, s, j, 16);
            float4 hv = __ldg((const float4*)(g_h + (size_t)ss * 64) + ln);
            unsigned long long cc = pk2(c, c);
            fma2(acc01, pk2(hv.x, hv.y), cc);
            fma2(acc23, pk2(hv.z, hv.w), cc);
        }
    } else {
        for (int base = row; base < end; base += 16) {
            int i = base + ln;
            int s = 0; float num = 0.f;
            if (i < end) {
                s = __ldg(&g_csr_src[i]);
                float v = __ldg(&g_as[s]) + ad;
                v = fmaxf(v, 0.2f * v);
                num = __expf(v - m);
            }
            den += num;
            int cnt = min(16, end - base);
            int j = 0;
            for (; j + 4 <= cnt; j += 4) {
                float c0 = __shfl_sync(seg_mask, num, j + 0, 16);
                float c1 = __shfl_sync(seg_mask, num, j + 1, 16);
                float c2 = __shfl_sync(seg_mask, num, j + 2, 16);
                float c3 = __shfl_sync(seg_mask, num, j + 3, 16);
                int  s0 = __shfl_sync(seg_mask, s, j + 0, 16);
                int  s1 = __shfl_sync(seg_mask, s, j + 1, 16);
                int  s2 = __shfl_sync(seg_mask, s, j + 2, 16);
                int  s3 = __shfl_sync(seg_mask, s, j + 3, 16);
                float4 h0 = __ldg((const float4*)(g_h + (size_t)s0 * 64) + ln);
                float4 h1 = __ldg((const float4*)(g_h + (size_t)s1 * 64) + ln);
                float4 h2 = __ldg((const float4*)(g_h + (size_t)s2 * 64) + ln);
                float4 h3 = __ldg((const float4*)(g_h + (size_t)s3 * 64) + ln);
                fma2(acc01, pk2(h0.x, h0.y), pk2(c0, c0));
                fma2(acc23, pk2(h0.z, h0.w), pk2(c0, c0));
                fma2(acc01, pk2(h1.x, h1.y), pk2(c1, c1));
                fma2(acc23, pk2(h1.z, h1.w), pk2(c1, c1));
                fma2(acc01, pk2(h2.x, h2.y), pk2(c2, c2));
                fma2(acc23, pk2(h2.z, h2.w), pk2(c2, c2));
                fma2(acc01, pk2(h3.x, h3.y), pk2(c3, c3));
                fma2(acc23, pk2(h3.z, h3.w), pk2(c3, c3));
            }
            for (; j < cnt; j++) {
                float c = __shfl_sync(seg_mask, num, j, 16);
                int  ss = __shfl_sync(seg_mask, s, j, 16);
                float4 hv = __ldg((const float4*)(g_h + (size_t)ss * 64) + ln);
                unsigned long long cc = pk2(c, c);
                fma2(acc01, pk2(hv.x, hv.y), cc);
                fma2(acc23, pk2(hv.z, hv.w), cc);
            }
        }
    }
#pragma unroll
    for (int o = 8; o; o >>= 1) den += __shfl_xor_sync(seg_mask, den, o, 16);

    float inv = 1.f / (den + 1e-16f);
    float4 a, b4 = ((const float4*)b)[ln];
    unpk2(acc01, a.x, a.y);
    unpk2(acc23, a.z, a.w);
    float4 o4;
    o4.x = fmaxf(a.x * inv + b4.x, 0.f);
    o4.y = fmaxf(a.y * inv + b4.y, 0.f);
    o4.z = fmaxf(a.z * inv + b4.z, 0.f);
    o4.w = fmaxf(a.w * inv + b4.w, 0.f);
    *((float4*)(g_act + (size_t)node * 64) + ln) = o4;
}

// ================= pooling / head =================
__global__ void k_pool(const int* __restrict__ batch) {
    int n0 = blockIdx.x * 128;
    int c = threadIdx.x;          // 0..63
    int nend = min(n0 + 128, NN);
    float cur = 0.f; int curg = -1;
    for (int n = n0 + threadIdx.y; n < nend; n += 4) {
        int g = batch[n];
        float v = g_act[(size_t)n * 64 + c];
        if (g != curg) {
            if (curg >= 0) atomicMaxF(&g_pool[curg * 64 + c], cur);
            curg = g; cur = v;
        } else {
            cur = fmaxf(cur, v);
        }
    }
    if (curg >= 0) atomicMaxF(&g_pool[curg * 64 + c], cur);
}

__global__ void k_head(const float* __restrict__ l0W, const float* __restrict__ l0b,
                       const float* __restrict__ l1W, const float* __restrict__ l1b,
                       float* __restrict__ out) {
    int g = blockIdx.x;
    int c = threadIdx.x;   // 0..63
    __shared__ float red[2];

    float acc = l0b[c];
#pragma unroll 8
    for (int k = 0; k < 64; k++) acc += g_pool[g * 64 + k] * l0W[k * 64 + c];
    float hp = fmaxf(acc, 0.f);
    float nw = g_news[g * 64 + c];

    float p = hp * l1W[c] + nw * l1W[64 + c];
#pragma unroll
    for (int o = 16; o; o >>= 1) p += __shfl_xor_sync(0xFFFFFFFFu, p, o);
    if ((c & 31) == 0) red[c >> 5] = p;
    __syncthreads();
    if (c == 0) {
        float z = red[0] + red[1] + l1b[0];
        out[g] = 1.f / (1.f + __expf(-z));
    }
}

// ================= launch =================
extern "C" void kernel_launch(void* const* d_in, const int* in_sizes, int n_in,
                              void* d_out, int out_size) {
    const float* x      = (const float*)d_in[0];
    const int*   adj    = (const int*)d_in[1];
    const int*   batch  = (const int*)d_in[2];
    const float* W1     = (const float*)d_in[3];
    const float* asrc1  = (const float*)d_in[4];
    const float* adst1  = (const float*)d_in[5];
    const float* b1     = (const float*)d_in[6];
    const float* W2     = (const float*)d_in[7];
    const float* asrc2  = (const float*)d_in[8];
    const float* adst2  = (const float*)d_in[9];
    const float* b2     = (const float*)d_in[10];
    const float* W3     = (const float*)d_in[11];
    const float* asrc3  = (const float*)d_in[12];
    const float* adst3  = (const float*)d_in[13];
    const float* b3     = (const float*)d_in[14];
    const float* lnW    = (const float*)d_in[15];
    const float* lnb    = (const float*)d_in[16];
    const float* l0W    = (const float*)d_in[17];
    const float* l0b    = (const float*)d_in[18];
    const float* l1W    = (const float*)d_in[19];
    const float* l1b    = (const float*)d_in[20];
    float* out = (float*)d_out;

    const int* src = adj;
    const int* dst = adj + EE;

    void* p_deg = nullptr;
    cudaGetSymbolAddress(&p_deg, g_deg);

    const int GEMM_GRID  = (NN + 127) / 128;          // 782
    const int EDGE_GRID  = (ET + 255) / 256;          // 4297
    const int AGG_GRID   = (NN * 16 + 255) / 256;     // 6250 (16 lanes per node)

    // ---- fork: CSR build + root/news head branch on s2, gemm1 on main ----
    cudaStream_t s2;
    cudaStreamCreateWithFlags(&s2, cudaStreamNonBlocking);
    cudaEvent_t evF, evJ;
    cudaEventCreateWithFlags(&evF, cudaEventDisableTiming);
    cudaEventCreateWithFlags(&evJ, cudaEventDisableTiming);

    cudaEventRecord(evF, 0);                 // fork point on capture stream
    cudaStreamWaitEvent(s2, evF, 0);

    // branch B (s2): CSR build + root + news — all independent of the layer chain
    cudaMemsetAsync(p_deg, 0, NN * sizeof(int), s2);
    k_hist<<<EDGE_GRID, 256, 0, s2>>>(dst);
    k_scan_block<<<NBLK, 256, 0, s2>>>();            // also inits pool/root
    k_scan_add<<<NBLK, 256, 0, s2>>>();
    k_scatter<<<EDGE_GRID, 256, 0, s2>>>(src, dst);
    k_root<<<NBLK, 256, 0, s2>>>(batch);             // after scan_block's root init
    k_news<<<GG, 64, 0, s2>>>(x, lnW, lnb);
    cudaEventRecord(evJ, s2);

    // branch A (main stream): gemm1 — needs only x, W1
    k_gemm<128><<<GEMM_GRID, 256>>>(x, W1, asrc1, adst1);

    cudaStreamWaitEvent(0, evJ, 0);          // join before agg1

    // ---- serial layer chain ----
    k_gat_agg<<<AGG_GRID, 256>>>(b1);
    k_gemm<64><<<GEMM_GRID, 256>>>(nullptr, W2, asrc2, adst2);
    k_gat_agg<<<AGG_GRID, 256>>>(b2);
    k_gemm<64><<<GEMM_GRID, 256>>>(nullptr, W3, asrc3, adst3);
    k_gat_agg<<<AGG_GRID, 256>>>(b3);

    // ---- head ----
    k_pool<<<(NN + 127) / 128, dim3(64, 4)>>>(batch);
    k_head<<<GG, 64>>>(l0W, l0b, l1W, l1b, out);

    cudaEventDestroy(evF);
    cudaEventDestroy(evJ);
    cudaStreamDestroy(s2);
}